// round 11
// baseline (speedup 1.0000x reference)
#include <cuda_runtime.h>

#define HID   128
#define NSTEP 128
#define MROWS 16
#define NTHR  256
#define HSTR  20          // act row stride in floats
#define NEGS  0.2f

// ---- dynamic smem layout (float offsets) ----
#define WB0   0
#define WB1   16384
#define HB_F  32768
#define HT_F  (HB_F + HID * HSTR)
#define HB_P  (HT_F + HID * HSTR)
#define HT_P  (HB_P + HID * HSTR)
#define XST   (HT_P + HID * HSTR)     // xsT[12][16]
#define DSO   (XST + 12 * 16)         // delta[16]
#define TBLW  (DSO + 16)              // u64[8]: next-layer weight ptrs
#define TBLB  (TBLW + 16)             // u64[8]: bias ptrs
#define SMEM_FLOATS (TBLB + 16)
#define SMEM_BYTES  (SMEM_FLOATS * 4)

typedef unsigned long long u64;

// ---------- packed fp32x2 helpers ----------
__device__ __forceinline__ u64 ffma2(u64 x, u64 y, u64 c) {
    u64 d;
    asm("fma.rn.f32x2 %0, %1, %2, %3;" : "=l"(d) : "l"(x), "l"(y), "l"(c));
    return d;
}
__device__ __forceinline__ u64 pack2(float lo, float hi) {
    u64 d;
    asm("mov.b64 %0, {%1, %2};" : "=l"(d) : "f"(lo), "f"(hi));
    return d;
}
__device__ __forceinline__ void unpack2(u64 v, float& lo, float& hi) {
    asm("mov.b64 {%0, %1}, %2;" : "=f"(lo), "=f"(hi) : "l"(v));
}

// ---------- cp.async ----------
__device__ __forceinline__ void cp_async16(unsigned dst, const void* src) {
    asm volatile("cp.async.cg.shared.global [%0], [%1], 16;" :: "r"(dst), "l"(src));
}
__device__ __forceinline__ void cp_commit() {
    asm volatile("cp.async.commit_group;" ::: "memory");
}
__device__ __forceinline__ void cp_wait_all() {
    asm volatile("cp.async.wait_group 0;" ::: "memory");
}

// 64KB weight matrix (128 rows x 32 float4-quads) global -> smem.
// Quad q (0..31) of row k stored at pos = ((q>>1) ^ ((k>>5)&3)) | ((q&1)<<4):
// even quads -> positions 0..15, odd -> 16..31, low bits XOR'd by k-quarter.
// Makes both the lo-quad and hi-quad LDS.128 reads bank-conflict-free.
__device__ __forceinline__ void prefetch_w(const float* __restrict__ src,
                                           float* dstf, int tid) {
    unsigned dstb = (unsigned)__cvta_generic_to_shared(dstf);
#pragma unroll
    for (int i = 0; i < 16; ++i) {
        const int idx = tid + i * NTHR;        // float4 index 0..4095
        const int k   = idx >> 5;              // row 0..127
        const int q   = idx & 31;              // quad within row
        const int pos = ((q >> 1) ^ ((k >> 5) & 3)) | ((q & 1) << 4);
        cp_async16(dstb + (unsigned)(k * 32 + pos) * 16,
                   (const char*)src + (size_t)idx * 16);
    }
}

// Accumulators: a[jp][m] = f32x2 pair (row j0+2jp, row j0+2jp+1) at m-col m0+m.
struct Acc { u64 a[4][4]; };
__device__ __forceinline__ void acc_zero(Acc& A) {
#pragma unroll
    for (int j = 0; j < 4; ++j)
#pragma unroll
        for (int m = 0; m < 4; ++m) A.a[j][m] = 0ull;
}

// Partial GEMM over this thread's 32-k quarter.
// Weight pairs (j,j+1) come directly from float4 register pairs (movs elided);
// only the 4 activation duplications are real MOVs.
__device__ __forceinline__ void mm_pass(Acc& A,
                                        const float* __restrict__ w_lo,
                                        const float* __restrict__ w_hi,
                                        const float* __restrict__ pact) {
#pragma unroll 2
    for (int kk = 0; kk < 32; ++kk) {
        const float4 wl = *reinterpret_cast<const float4*>(w_lo + kk * HID);
        const float4 wh = *reinterpret_cast<const float4*>(w_hi + kk * HID);
        const float4 av = *reinterpret_cast<const float4*>(pact + kk * HSTR);
        u64 wp0 = pack2(wl.x, wl.y);   // natural register pair (elidable)
        u64 wp1 = pack2(wl.z, wl.w);
        u64 wp2 = pack2(wh.x, wh.y);
        u64 wp3 = pack2(wh.z, wh.w);
        u64 a0 = pack2(av.x, av.x);    // real dup movs (4)
        u64 a1 = pack2(av.y, av.y);
        u64 a2 = pack2(av.z, av.z);
        u64 a3 = pack2(av.w, av.w);
        A.a[0][0] = ffma2(wp0, a0, A.a[0][0]);
        A.a[0][1] = ffma2(wp0, a1, A.a[0][1]);
        A.a[0][2] = ffma2(wp0, a2, A.a[0][2]);
        A.a[0][3] = ffma2(wp0, a3, A.a[0][3]);
        A.a[1][0] = ffma2(wp1, a0, A.a[1][0]);
        A.a[1][1] = ffma2(wp1, a1, A.a[1][1]);
        A.a[1][2] = ffma2(wp1, a2, A.a[1][2]);
        A.a[1][3] = ffma2(wp1, a3, A.a[1][3]);
        A.a[2][0] = ffma2(wp2, a0, A.a[2][0]);
        A.a[2][1] = ffma2(wp2, a1, A.a[2][1]);
        A.a[2][2] = ffma2(wp2, a2, A.a[2][2]);
        A.a[2][3] = ffma2(wp2, a3, A.a[2][3]);
        A.a[3][0] = ffma2(wp3, a0, A.a[3][0]);
        A.a[3][1] = ffma2(wp3, a1, A.a[3][1]);
        A.a[3][2] = ffma2(wp3, a2, A.a[3][2]);
        A.a[3][3] = ffma2(wp3, a3, A.a[3][3]);
    }
}

// Butterfly k-reduction across the 4 lane k-quarters (lane bits 3,4).
__device__ __forceinline__ void reduce_acc(Acc& A) {
#pragma unroll
    for (int jp = 0; jp < 4; ++jp)
#pragma unroll
        for (int m = 0; m < 4; ++m) {
            float lo, hi;
            unpack2(A.a[jp][m], lo, hi);
            lo += __shfl_xor_sync(0xffffffffu, lo, 8);
            hi += __shfl_xor_sync(0xffffffffu, hi, 8);
            lo += __shfl_xor_sync(0xffffffffu, lo, 16);
            hi += __shfl_xor_sync(0xffffffffu, hi, 16);
            A.a[jp][m] = pack2(lo, hi);
        }
}

// bias + optional residual + leaky; lane kq stores rows j0+2kq, j0+2kq+1.
// Pair selection uses value SELs (no runtime register-array indexing!).
__device__ __forceinline__ void epi(Acc& A, const float* __restrict__ bias,
                                    float* __restrict__ dst,
                                    const float* __restrict__ res, bool hasRes,
                                    int j0, int kq, int qoff) {
    reduce_acc(A);
    u64 p[4];
#pragma unroll
    for (int m = 0; m < 4; ++m) {
        const u64 lo = (kq & 1) ? A.a[1][m] : A.a[0][m];
        const u64 hi = (kq & 1) ? A.a[3][m] : A.a[2][m];
        p[m] = (kq & 2) ? hi : lo;
    }
    const int r1 = j0 + 2 * kq;
    const int r2 = r1 + 1;
    float x0, x1, x2, x3, y0, y1, y2, y3;
    unpack2(p[0], x0, y0);
    unpack2(p[1], x1, y1);
    unpack2(p[2], x2, y2);
    unpack2(p[3], x3, y3);
    const float b1 = __ldg(bias + r1);
    const float b2 = __ldg(bias + r2);
    x0 += b1; x1 += b1; x2 += b1; x3 += b1;
    y0 += b2; y1 += b2; y2 += b2; y3 += b2;
    if (hasRes) {
        const float4 rA = *reinterpret_cast<const float4*>(res + r1 * HSTR + qoff);
        const float4 rB = *reinterpret_cast<const float4*>(res + r2 * HSTR + qoff);
        x0 += rA.x; x1 += rA.y; x2 += rA.z; x3 += rA.w;
        y0 += rB.x; y1 += rB.y; y2 += rB.z; y3 += rB.w;
    }
    x0 = fmaxf(x0, NEGS * x0); x1 = fmaxf(x1, NEGS * x1);
    x2 = fmaxf(x2, NEGS * x2); x3 = fmaxf(x3, NEGS * x3);
    y0 = fmaxf(y0, NEGS * y0); y1 = fmaxf(y1, NEGS * y1);
    y2 = fmaxf(y2, NEGS * y2); y3 = fmaxf(y3, NEGS * y3);
    *reinterpret_cast<float4*>(dst + r1 * HSTR + qoff) = make_float4(x0, x1, x2, x3);
    *reinterpret_cast<float4*>(dst + r2 * HSTR + qoff) = make_float4(y0, y1, y2, y3);
}

// Small-K input layer: each thread computes its 2 rows x 4 m fully (no k-split).
__device__ __forceinline__ void input_layer(const float* __restrict__ Win,
                                            const float* __restrict__ bin,
                                            const float* __restrict__ xsT,
                                            int coff, int K,
                                            float* __restrict__ dst,
                                            int j0, int kq, int m0, int qoff) {
    const int r1 = j0 + kq * 2;
    const int r2 = r1 + 1;
    float y1[4] = {}, y2[4] = {};
    for (int k = 0; k < K; ++k) {
        const float w1 = __ldg(Win + k * HID + r1);
        const float w2 = __ldg(Win + k * HID + r2);
        const float4 a = *reinterpret_cast<const float4*>(xsT + (coff + k) * 16 + m0);
        y1[0] = fmaf(w1, a.x, y1[0]); y1[1] = fmaf(w1, a.y, y1[1]);
        y1[2] = fmaf(w1, a.z, y1[2]); y1[3] = fmaf(w1, a.w, y1[3]);
        y2[0] = fmaf(w2, a.x, y2[0]); y2[1] = fmaf(w2, a.y, y2[1]);
        y2[2] = fmaf(w2, a.z, y2[2]); y2[3] = fmaf(w2, a.w, y2[3]);
    }
    const float b1 = __ldg(bin + r1);
    const float b2 = __ldg(bin + r2);
#pragma unroll
    for (int i = 0; i < 4; ++i) {
        y1[i] += b1; y1[i] = fmaxf(y1[i], NEGS * y1[i]);
        y2[i] += b2; y2[i] = fmaxf(y2[i], NEGS * y2[i]);
    }
    *reinterpret_cast<float4*>(dst + r1 * HSTR + qoff) = make_float4(y1[0], y1[1], y1[2], y1[3]);
    *reinterpret_cast<float4*>(dst + r2 * HSTR + qoff) = make_float4(y2[0], y2[1], y2[2], y2[3]);
}

__global__ void __launch_bounds__(NTHR, 1)
hedger_kernel(const float* __restrict__ feats,
              const float* __restrict__ fw_in, const float* __restrict__ fb_in,
              const float* __restrict__ fr1_w1, const float* __restrict__ fr1_b1,
              const float* __restrict__ fr1_w2, const float* __restrict__ fr1_b2,
              const float* __restrict__ fr2_w1, const float* __restrict__ fr2_b1,
              const float* __restrict__ fr2_w2, const float* __restrict__ fr2_b2,
              const float* __restrict__ pw_in, const float* __restrict__ pb_in,
              const float* __restrict__ pr1_w1, const float* __restrict__ pr1_b1,
              const float* __restrict__ pr1_w2, const float* __restrict__ pr1_b2,
              const float* __restrict__ pr2_w1, const float* __restrict__ pr2_b1,
              const float* __restrict__ pr2_w2, const float* __restrict__ pr2_b2,
              const float* __restrict__ cw1, const float* __restrict__ cb1,
              const float* __restrict__ cw2, const float* __restrict__ cb2,
              float* __restrict__ out) {
    extern __shared__ float sm[];
    float* wb0  = sm + WB0;
    float* wb1  = sm + WB1;
    float* hb_f = sm + HB_F;
    float* ht_f = sm + HT_F;
    float* hb_p = sm + HB_P;
    float* ht_p = sm + HT_P;
    float* xsT  = sm + XST;
    float* ds   = sm + DSO;
    u64*   twn  = reinterpret_cast<u64*>(sm + TBLW);
    u64*   tbp  = reinterpret_cast<u64*>(sm + TBLB);

    const int tid  = threadIdx.x;
    const int lane = tid & 31;
    const int warp = tid >> 5;
    const int kq   = lane >> 3;               // 0..3 k-quarter
    const int t    = lane & 7;
    const int p    = warp * 8 + t;            // 0..63 output-tile position
    const int j0   = (p & 15) * 8;            // 8-row block
    const int mq   = p >> 4;                  // 0..3 m-quad
    const int m0   = mq * 4;
    const int b0   = blockIdx.x * MROWS;

    // swizzle-resolved per-thread constants
    const int wlo_off = (((j0 >> 3) ^ kq) << 2);        // lo quad position * 4 floats
    const int whi_off = wlo_off + 64;                   // odd quads live at +16 quads
    const int wrow0   = kq * 32 * HID;
    const int aoff    = ((mq ^ kq) & 3) * 4;            // act read quad for this k-quarter
    const int arow0   = kq * 32 * HSTR;
    const int qoff    = ((mq ^ ((j0 >> 5) & 3)) & 3) * 4;  // act store quad

    if (tid == 0) {
        twn[0] = (u64)fr1_w2; twn[1] = (u64)fr2_w1; twn[2] = (u64)fr2_w2;
        twn[3] = (u64)pr1_w1; twn[4] = (u64)pr1_w2; twn[5] = (u64)pr2_w1;
        twn[6] = (u64)pr2_w2; twn[7] = (u64)cw1;
        tbp[0] = (u64)fr1_b1; tbp[1] = (u64)fr1_b2; tbp[2] = (u64)fr2_b1;
        tbp[3] = (u64)fr2_b2; tbp[4] = (u64)pr1_b1; tbp[5] = (u64)pr1_b2;
        tbp[6] = (u64)pr2_b1; tbp[7] = (u64)pr2_b2;
    }
    const float cb2v = __ldg(cb2);

    prefetch_w(fr1_w1, wb0, tid);
    cp_commit();

    for (int n = 0; n < NSTEP; ++n) {
        // ---- features -> xsT[c][m]; recurrent delta into col 3 ----
        if (tid < MROWS * 12) {
            const int r = tid / 12, c = tid % 12;
            float v = feats[((size_t)(b0 + r) * NSTEP + n) * 12 + c];
            if (c == 3 && n > 0) v = ds[r];
            xsT[c * 16 + r] = v;
        }
        __syncthreads();   // xsT + ds + (step 0: tables) visible

        // ---- input layers ----
        input_layer(fw_in, fb_in, xsT, 0, 4, hb_f, j0, kq, m0, qoff);
        input_layer(pw_in, pb_in, xsT, 4, 8, hb_p, j0, kq, m0, qoff);

        // ---- 8 tower layers, double-buffered weights ----
#pragma unroll 1
        for (int L = 0; L < 8; ++L) {
            float* wc = (L & 1) ? wb1 : wb0;
            float* pf = (L & 1) ? wb0 : wb1;
            float* hb = (L < 4) ? hb_f : hb_p;
            float* ht = (L < 4) ? ht_f : ht_p;
            const bool odd = (L & 1) != 0;
            const float* src = odd ? ht : hb;
            float*       dst = odd ? hb : ht;
            const float* bias  = (const float*)tbp[L];
            const float* wnext = (const float*)twn[L];

            cp_wait_all();
            __syncthreads();            // weights staged + prev-layer acts written
            prefetch_w(wnext, pf, tid);
            cp_commit();

            Acc A; acc_zero(A);
            mm_pass(A, wc + wrow0 + wlo_off, wc + wrow0 + whi_off, src + arow0 + aoff);
            epi(A, bias, dst, dst, odd, j0, kq, qoff);
        }

        // ---- combiner: concat(fe, pe) @ cw1 + cb1 -> ht_f ----
        {
            Acc A; acc_zero(A);
            cp_wait_all();
            __syncthreads();
            prefetch_w(cw1 + HID * HID, wb1, tid);
            cp_commit();
            mm_pass(A, wb0 + wrow0 + wlo_off, wb0 + wrow0 + whi_off, hb_f + arow0 + aoff);

            cp_wait_all();
            __syncthreads();
            prefetch_w(fr1_w1, wb0, tid);     // wrap for next step
            cp_commit();
            mm_pass(A, wb1 + wrow0 + wlo_off, wb1 + wrow0 + whi_off, hb_p + arow0 + aoff);
            epi(A, cb1, ht_f, nullptr, false, j0, kq, qoff);
        }
        __syncthreads();

        // ---- head: sigmoid(hc @ cw2 + cb2) ----
        {
            const int m   = tid >> 4;        // 0..15
            const int seg = tid & 15;        // 16-way j split
            const int mqh = (m >> 2);
            const int mlo = (m & 3);
            float pacc = 0.0f;
#pragma unroll
            for (int jj = 0; jj < 8; ++jj) {
                const int j = seg * 8 + jj;
                const int qh = ((mqh ^ ((j >> 5) & 3)) & 3) * 4;
                pacc += ht_f[j * HSTR + qh + mlo] * __ldg(cw2 + j);
            }
            pacc += __shfl_down_sync(0xffffffffu, pacc, 8, 16);
            pacc += __shfl_down_sync(0xffffffffu, pacc, 4, 16);
            pacc += __shfl_down_sync(0xffffffffu, pacc, 2, 16);
            pacc += __shfl_down_sync(0xffffffffu, pacc, 1, 16);
            if (seg == 0) {
                const float d = 1.0f / (1.0f + expf(-(pacc + cb2v)));
                ds[m] = d;
                out[(size_t)(b0 + m) * NSTEP + n] = d;
            }
        }
        __syncthreads();   // ds visible to next step's feature stage
    }
}

extern "C" void kernel_launch(void* const* d_in, const int* in_sizes, int n_in,
                              void* d_out, int out_size) {
    const float* feats  = (const float*)d_in[0];
    const float* fw_in  = (const float*)d_in[1];
    const float* fb_in  = (const float*)d_in[2];
    const float* fr1_w1 = (const float*)d_in[3];
    const float* fr1_b1 = (const float*)d_in[4];
    const float* fr1_w2 = (const float*)d_in[5];
    const float* fr1_b2 = (const float*)d_in[6];
    const float* fr2_w1 = (const float*)d_in[7];
    const float* fr2_b1 = (const float*)d_in[8];
    const float* fr2_w2 = (const float*)d_in[9];
    const float* fr2_b2 = (const float*)d_in[10];
    const float* pw_in  = (const float*)d_in[11];
    const float* pb_in  = (const float*)d_in[12];
    const float* pr1_w1 = (const float*)d_in[13];
    const float* pr1_b1 = (const float*)d_in[14];
    const float* pr1_w2 = (const float*)d_in[15];
    const float* pr1_b2 = (const float*)d_in[16];
    const float* pr2_w1 = (const float*)d_in[17];
    const float* pr2_b1 = (const float*)d_in[18];
    const float* pr2_w2 = (const float*)d_in[19];
    const float* pr2_b2 = (const float*)d_in[20];
    const float* cw1    = (const float*)d_in[21];
    const float* cb1    = (const float*)d_in[22];
    const float* cw2    = (const float*)d_in[23];
    const float* cb2    = (const float*)d_in[24];

    cudaFuncSetAttribute(hedger_kernel,
                         cudaFuncAttributeMaxDynamicSharedMemorySize, SMEM_BYTES);

    hedger_kernel<<<2048 / MROWS, NTHR, SMEM_BYTES>>>(
        feats,
        fw_in, fb_in,
        fr1_w1, fr1_b1, fr1_w2, fr1_b2,
        fr2_w1, fr2_b1, fr2_w2, fr2_b2,
        pw_in, pb_in,
        pr1_w1, pr1_b1, pr1_w2, pr1_b2,
        pr2_w1, pr2_b1, pr2_w2, pr2_b2,
        cw1, cb1, cw2, cb2,
        (float*)d_out);
}

// round 12
// speedup vs baseline: 1.8023x; 1.8023x over previous
#include <cuda_runtime.h>

#define HID   128
#define NSTEP 128
#define MROWS 16
#define NTHR  256
#define NEGS  0.2f

// ---- dynamic smem layout (float offsets) ----
#define WB0   0
#define WB1   16384
#define HB_F  32768            // act buffers: 64 blocks * 32 floats = 2048 floats
#define HT_F  (HB_F + 2048)
#define HB_P  (HT_F + 2048)
#define HT_P  (HB_P + 2048)
#define XST   (HT_P + 2048)    // xsT[12][16]
#define DSO   (XST + 192)      // delta[16]
#define SMEM_FLOATS (DSO + 16)
#define SMEM_BYTES  (SMEM_FLOATS * 4)

typedef unsigned long long u64;

// ---------- packed fp32x2 helpers ----------
__device__ __forceinline__ u64 ffma2(u64 x, u64 y, u64 c) {
    u64 d;
    asm("fma.rn.f32x2 %0, %1, %2, %3;" : "=l"(d) : "l"(x), "l"(y), "l"(c));
    return d;
}
__device__ __forceinline__ u64 pack2(float lo, float hi) {
    u64 d;
    asm("mov.b64 %0, {%1, %2};" : "=l"(d) : "f"(lo), "f"(hi));
    return d;
}
__device__ __forceinline__ void unpack2(u64 v, float& lo, float& hi) {
    asm("mov.b64 {%0, %1}, %2;" : "=f"(lo), "=f"(hi) : "l"(v));
}

// ---------- cp.async ----------
__device__ __forceinline__ void cp_async16(unsigned dst, const void* src) {
    asm volatile("cp.async.cg.shared.global [%0], [%1], 16;" :: "r"(dst), "l"(src));
}
__device__ __forceinline__ void cp_commit() {
    asm volatile("cp.async.commit_group;" ::: "memory");
}
__device__ __forceinline__ void cp_wait_all() {
    asm volatile("cp.async.wait_group 0;" ::: "memory");
}

// Plain 64KB weight copy (row-major [k][j], stride 128 floats). No swizzle:
// mainloop weight reads are 128B-contiguous per 8-lane phase already.
__device__ __forceinline__ void prefetch_w(const float* __restrict__ src,
                                           float* dstf, int tid) {
    unsigned dstb = (unsigned)__cvta_generic_to_shared(dstf);
#pragma unroll
    for (int i = 0; i < 16; ++i) {
        const int off = (tid + i * NTHR) * 16;   // bytes
        cp_async16(dstb + off, (const char*)src + off);
    }
}

// Activation layout: two 16-float rows per 128B block.
// addr(r, m) = (r>>1)*32 + slot*4 + (m&3),
// slot = ((mq + (r>>2) + (r>>6)) & 3) | ((r&1)<<2),  mq = m>>2.
// The r>>6 term separates the two k-half broadcast addresses into distinct banks.
__device__ __forceinline__ int act_addr(int r, int m) {
    const int slot = ((((m >> 2) + (r >> 2) + (r >> 6)) & 3)) | ((r & 1) << 2);
    return (r >> 1) * 32 + slot * 4 + (m & 3);
}

// Accumulators: a[jp][mi] = f32x2 (row j0+2jp, row j0+2jp+1) at m-col m0+mi.
struct Acc { u64 a[2][4]; };
__device__ __forceinline__ void acc_zero(Acc& A) {
#pragma unroll
    for (int j = 0; j < 2; ++j)
#pragma unroll
        for (int m = 0; m < 4; ++m) A.a[j][m] = 0ull;
}

// Partial GEMM over this thread's 64-row k-half (rows k0..k0+63).
// Weights: [k][j] row-major, stride HID. Acts: swizzled layout above.
__device__ __forceinline__ void mm_pass(Acc& A, const float* __restrict__ wb,
                                        const float* __restrict__ ab,
                                        int k0, int j0, int mq) {
    const int c6 = (k0 >> 6) & 1;       // constant within the half
#pragma unroll 4
    for (int kk = 0; kk < 64; ++kk) {
        const int k = k0 + kk;
        const float4 w4 = *reinterpret_cast<const float4*>(wb + k * HID + j0);
        const int slot = (((mq + (k >> 2) + c6) & 3)) | ((k & 1) << 2);
        const float4 a4 = *reinterpret_cast<const float4*>(ab + (k >> 1) * 32 + slot * 4);
        const u64 wp0 = pack2(w4.x, w4.y);   // natural register pairs (elidable)
        const u64 wp1 = pack2(w4.z, w4.w);
        const u64 a0 = pack2(a4.x, a4.x);    // 4 real dup movs
        const u64 a1 = pack2(a4.y, a4.y);
        const u64 a2 = pack2(a4.z, a4.z);
        const u64 a3 = pack2(a4.w, a4.w);
        A.a[0][0] = ffma2(wp0, a0, A.a[0][0]);
        A.a[0][1] = ffma2(wp0, a1, A.a[0][1]);
        A.a[0][2] = ffma2(wp0, a2, A.a[0][2]);
        A.a[0][3] = ffma2(wp0, a3, A.a[0][3]);
        A.a[1][0] = ffma2(wp1, a0, A.a[1][0]);
        A.a[1][1] = ffma2(wp1, a1, A.a[1][1]);
        A.a[1][2] = ffma2(wp1, a2, A.a[1][2]);
        A.a[1][3] = ffma2(wp1, a3, A.a[1][3]);
    }
}

// k-half reduction (lane ^ 16) + bias + optional residual + leaky + store.
// kh=0 lane stores rows j0,j0+1 (jp 0); kh=1 stores j0+2,j0+3 (jp 1).
__device__ __forceinline__ void epi(Acc& A, const float* __restrict__ bias,
                                    float* __restrict__ dst,
                                    const float* __restrict__ res, bool hasRes,
                                    int j0, int kh, int mq) {
#pragma unroll
    for (int jp = 0; jp < 2; ++jp)
#pragma unroll
        for (int m = 0; m < 4; ++m) {
            float lo, hi;
            unpack2(A.a[jp][m], lo, hi);
            lo += __shfl_xor_sync(0xffffffffu, lo, 16);
            hi += __shfl_xor_sync(0xffffffffu, hi, 16);
            A.a[jp][m] = pack2(lo, hi);
        }
    u64 v0 = kh ? A.a[1][0] : A.a[0][0];
    u64 v1 = kh ? A.a[1][1] : A.a[0][1];
    u64 v2 = kh ? A.a[1][2] : A.a[0][2];
    u64 v3 = kh ? A.a[1][3] : A.a[0][3];
    const int r1 = j0 + 2 * kh;
    const int r2 = r1 + 1;
    float x0, x1, x2, x3, y0, y1, y2, y3;
    unpack2(v0, x0, y0); unpack2(v1, x1, y1);
    unpack2(v2, x2, y2); unpack2(v3, x3, y3);
    const float b1 = __ldg(bias + r1);
    const float b2 = __ldg(bias + r2);
    x0 += b1; x1 += b1; x2 += b1; x3 += b1;
    y0 += b2; y1 += b2; y2 += b2; y3 += b2;
    const int a1o = act_addr(r1, mq * 4);
    const int a2o = act_addr(r2, mq * 4);
    if (hasRes) {
        const float4 rA = *reinterpret_cast<const float4*>(res + a1o);
        const float4 rB = *reinterpret_cast<const float4*>(res + a2o);
        x0 += rA.x; x1 += rA.y; x2 += rA.z; x3 += rA.w;
        y0 += rB.x; y1 += rB.y; y2 += rB.z; y3 += rB.w;
    }
    x0 = fmaxf(x0, NEGS * x0); x1 = fmaxf(x1, NEGS * x1);
    x2 = fmaxf(x2, NEGS * x2); x3 = fmaxf(x3, NEGS * x3);
    y0 = fmaxf(y0, NEGS * y0); y1 = fmaxf(y1, NEGS * y1);
    y2 = fmaxf(y2, NEGS * y2); y3 = fmaxf(y3, NEGS * y3);
    *reinterpret_cast<float4*>(dst + a1o) = make_float4(x0, x1, x2, x3);
    *reinterpret_cast<float4*>(dst + a2o) = make_float4(y0, y1, y2, y3);
}

template <bool RES>
__device__ __forceinline__ void full_layer(const float* __restrict__ Wsm,
                                           const float* __restrict__ b,
                                           const float* __restrict__ hin,
                                           float* __restrict__ hout,
                                           int k0, int j0, int kh, int mq) {
    Acc A; acc_zero(A);
    mm_pass(A, Wsm, hin, k0, j0, mq);
    epi(A, b, hout, hout, RES, j0, kh, mq);
}

// Small-K input layer: thread computes its 2 rows x 4 m fully.
__device__ __forceinline__ void input_layer(const float* __restrict__ Win,
                                            const float* __restrict__ bin,
                                            const float* __restrict__ xsT,
                                            int coff, int K,
                                            float* __restrict__ dst,
                                            int j0, int kh, int mq) {
    const int r1 = j0 + 2 * kh;
    const int r2 = r1 + 1;
    const int m0 = mq * 4;
    float y1[4] = {}, y2[4] = {};
    for (int k = 0; k < K; ++k) {
        const float w1 = __ldg(Win + k * HID + r1);
        const float w2 = __ldg(Win + k * HID + r2);
        const float4 a = *reinterpret_cast<const float4*>(xsT + (coff + k) * 16 + m0);
        y1[0] = fmaf(w1, a.x, y1[0]); y1[1] = fmaf(w1, a.y, y1[1]);
        y1[2] = fmaf(w1, a.z, y1[2]); y1[3] = fmaf(w1, a.w, y1[3]);
        y2[0] = fmaf(w2, a.x, y2[0]); y2[1] = fmaf(w2, a.y, y2[1]);
        y2[2] = fmaf(w2, a.z, y2[2]); y2[3] = fmaf(w2, a.w, y2[3]);
    }
    const float b1 = __ldg(bin + r1);
    const float b2 = __ldg(bin + r2);
#pragma unroll
    for (int i = 0; i < 4; ++i) {
        y1[i] += b1; y1[i] = fmaxf(y1[i], NEGS * y1[i]);
        y2[i] += b2; y2[i] = fmaxf(y2[i], NEGS * y2[i]);
    }
    *reinterpret_cast<float4*>(dst + act_addr(r1, m0)) = make_float4(y1[0], y1[1], y1[2], y1[3]);
    *reinterpret_cast<float4*>(dst + act_addr(r2, m0)) = make_float4(y2[0], y2[1], y2[2], y2[3]);
}

__global__ void __launch_bounds__(NTHR, 1)
hedger_kernel(const float* __restrict__ feats,
              const float* __restrict__ fw_in, const float* __restrict__ fb_in,
              const float* __restrict__ fr1_w1, const float* __restrict__ fr1_b1,
              const float* __restrict__ fr1_w2, const float* __restrict__ fr1_b2,
              const float* __restrict__ fr2_w1, const float* __restrict__ fr2_b1,
              const float* __restrict__ fr2_w2, const float* __restrict__ fr2_b2,
              const float* __restrict__ pw_in, const float* __restrict__ pb_in,
              const float* __restrict__ pr1_w1, const float* __restrict__ pr1_b1,
              const float* __restrict__ pr1_w2, const float* __restrict__ pr1_b2,
              const float* __restrict__ pr2_w1, const float* __restrict__ pr2_b1,
              const float* __restrict__ pr2_w2, const float* __restrict__ pr2_b2,
              const float* __restrict__ cw1, const float* __restrict__ cb1,
              const float* __restrict__ cw2, const float* __restrict__ cb2,
              float* __restrict__ out) {
    extern __shared__ float sm[];
    float* wb0  = sm + WB0;
    float* wb1  = sm + WB1;
    float* hb_f = sm + HB_F;
    float* ht_f = sm + HT_F;
    float* hb_p = sm + HB_P;
    float* ht_p = sm + HT_P;
    float* xsT  = sm + XST;
    float* ds   = sm + DSO;

    const int tid  = threadIdx.x;
    const int lane = tid & 31;
    const int warp = tid >> 5;
    const int kh   = lane >> 4;               // 0/1 k-half
    const int t    = lane & 15;
    const int j0   = ((warp & 1) * 16 + t) * 4;  // j-quad base, 0..124
    const int mq   = warp >> 1;               // 0..3 m-quad (per warp-pair)
    const int k0   = kh * 64;
    const int b0   = blockIdx.x * MROWS;

    const float cb2v = __ldg(cb2);
    const float* cw1_hi = cw1 + HID * HID;

    prefetch_w(fr1_w1, wb0, tid);
    cp_commit();

    for (int n = 0; n < NSTEP; ++n) {
        // ---- features -> xsT[c][m]; recurrent delta into col 3 ----
        if (tid < MROWS * 12) {
            const int r = tid / 12, c = tid % 12;
            float v = feats[((size_t)(b0 + r) * NSTEP + n) * 12 + c];
            if (c == 3 && n > 0) v = ds[r];
            xsT[c * 16 + r] = v;
        }
        __syncthreads();

        // ---- input layers (tiny K, weights L1-resident) ----
        input_layer(fw_in, fb_in, xsT, 0, 4, hb_f, j0, kh, mq);
        input_layer(pw_in, pb_in, xsT, 4, 8, hb_p, j0, kh, mq);

        // ---- 10 staged 64KB layers, double-buffered ----
        cp_wait_all(); __syncthreads();
        prefetch_w(fr1_w2, wb1, tid); cp_commit();
        full_layer<false>(wb0, fr1_b1, hb_f, ht_f, k0, j0, kh, mq);

        cp_wait_all(); __syncthreads();
        prefetch_w(fr2_w1, wb0, tid); cp_commit();
        full_layer<true >(wb1, fr1_b2, ht_f, hb_f, k0, j0, kh, mq);

        cp_wait_all(); __syncthreads();
        prefetch_w(fr2_w2, wb1, tid); cp_commit();
        full_layer<false>(wb0, fr2_b1, hb_f, ht_f, k0, j0, kh, mq);

        cp_wait_all(); __syncthreads();
        prefetch_w(pr1_w1, wb0, tid); cp_commit();
        full_layer<true >(wb1, fr2_b2, ht_f, hb_f, k0, j0, kh, mq);

        cp_wait_all(); __syncthreads();
        prefetch_w(pr1_w2, wb1, tid); cp_commit();
        full_layer<false>(wb0, pr1_b1, hb_p, ht_p, k0, j0, kh, mq);

        cp_wait_all(); __syncthreads();
        prefetch_w(pr2_w1, wb0, tid); cp_commit();
        full_layer<true >(wb1, pr1_b2, ht_p, hb_p, k0, j0, kh, mq);

        cp_wait_all(); __syncthreads();
        prefetch_w(pr2_w2, wb1, tid); cp_commit();
        full_layer<false>(wb0, pr2_b1, hb_p, ht_p, k0, j0, kh, mq);

        cp_wait_all(); __syncthreads();
        prefetch_w(cw1, wb0, tid); cp_commit();
        full_layer<true >(wb1, pr2_b2, ht_p, hb_p, k0, j0, kh, mq);

        // combiner: accumulate both halves of concat(fe, pe) @ cw1
        {
            Acc A; acc_zero(A);
            cp_wait_all(); __syncthreads();
            prefetch_w(cw1_hi, wb1, tid); cp_commit();
            mm_pass(A, wb0, hb_f, k0, j0, mq);        // fe @ cw1[0:128]

            cp_wait_all(); __syncthreads();
            prefetch_w(fr1_w1, wb0, tid); cp_commit();  // wrap: next step's L0
            mm_pass(A, wb1, hb_p, k0, j0, mq);        // pe @ cw1[128:256]
            epi(A, cb1, ht_f, nullptr, false, j0, kh, mq);
        }
        __syncthreads();

        // ---- head: sigmoid(hc @ cw2 + cb2) ----
        {
            const int m   = tid >> 4;        // 0..15
            const int seg = tid & 15;        // 16-way j split
            float pacc = 0.0f;
#pragma unroll
            for (int jj = 0; jj < 8; ++jj) {
                const int j = seg * 8 + jj;
                pacc += ht_f[act_addr(j, m)] * __ldg(cw2 + j);
            }
            pacc += __shfl_down_sync(0xffffffffu, pacc, 8, 16);
            pacc += __shfl_down_sync(0xffffffffu, pacc, 4, 16);
            pacc += __shfl_down_sync(0xffffffffu, pacc, 2, 16);
            pacc += __shfl_down_sync(0xffffffffu, pacc, 1, 16);
            if (seg == 0) {
                const float d = 1.0f / (1.0f + expf(-(pacc + cb2v)));
                ds[m] = d;
                out[(size_t)(b0 + m) * NSTEP + n] = d;
            }
        }
        __syncthreads();
    }
}

extern "C" void kernel_launch(void* const* d_in, const int* in_sizes, int n_in,
                              void* d_out, int out_size) {
    const float* feats  = (const float*)d_in[0];
    const float* fw_in  = (const float*)d_in[1];
    const float* fb_in  = (const float*)d_in[2];
    const float* fr1_w1 = (const float*)d_in[3];
    const float* fr1_b1 = (const float*)d_in[4];
    const float* fr1_w2 = (const float*)d_in[5];
    const float* fr1_b2 = (const float*)d_in[6];
    const float* fr2_w1 = (const float*)d_in[7];
    const float* fr2_b1 = (const float*)d_in[8];
    const float* fr2_w2 = (const float*)d_in[9];
    const float* fr2_b2 = (const float*)d_in[10];
    const float* pw_in  = (const float*)d_in[11];
    const float* pb_in  = (const float*)d_in[12];
    const float* pr1_w1 = (const float*)d_in[13];
    const float* pr1_b1 = (const float*)d_in[14];
    const float* pr1_w2 = (const float*)d_in[15];
    const float* pr1_b2 = (const float*)d_in[16];
    const float* pr2_w1 = (const float*)d_in[17];
    const float* pr2_b1 = (const float*)d_in[18];
    const float* pr2_w2 = (const float*)d_in[19];
    const float* pr2_b2 = (const float*)d_in[20];
    const float* cw1    = (const float*)d_in[21];
    const float* cb1    = (const float*)d_in[22];
    const float* cw2    = (const float*)d_in[23];
    const float* cb2    = (const float*)d_in[24];

    cudaFuncSetAttribute(hedger_kernel,
                         cudaFuncAttributeMaxDynamicSharedMemorySize, SMEM_BYTES);

    hedger_kernel<<<2048 / MROWS, NTHR, SMEM_BYTES>>>(
        feats,
        fw_in, fb_in,
        fr1_w1, fr1_b1, fr1_w2, fr1_b2,
        fr2_w1, fr2_b1, fr2_w2, fr2_b2,
        pw_in, pb_in,
        pr1_w1, pr1_b1, pr1_w2, pr1_b2,
        pr2_w1, pr2_b1, pr2_w2, pr2_b2,
        cw1, cb1, cw2, cb2,
        (float*)d_out);
}

// round 14
// speedup vs baseline: 1.8061x; 1.0021x over previous
#include <cuda_runtime.h>

#define HID   128
#define NSTEP 128
#define MROWS 16
#define NTHR  256
#define ASTR  20               // act row stride in floats (80B, 16B-aligned rows)
#define NEGS  0.2f

// ---- dynamic smem layout (float offsets) ----
#define WB0   0
#define WB1   16384
#define HB_F  32768            // 128*ASTR = 2560 floats each
#define HT_F  (HB_F + HID * ASTR)
#define HB_P  (HT_F + HID * ASTR)
#define HT_P  (HB_P + HID * ASTR)
#define XST   (HT_P + HID * ASTR)   // xsT[12][16]
#define DSO   (XST + 192)           // delta[16]
#define SMEM_FLOATS (DSO + 16)
#define SMEM_BYTES  (SMEM_FLOATS * 4)

typedef unsigned long long u64;

// ---------- packed fp32x2 helpers ----------
__device__ __forceinline__ u64 ffma2(u64 x, u64 y, u64 c) {
    u64 d;
    asm("fma.rn.f32x2 %0, %1, %2, %3;" : "=l"(d) : "l"(x), "l"(y), "l"(c));
    return d;
}
__device__ __forceinline__ u64 pack2(float lo, float hi) {
    u64 d;
    asm("mov.b64 %0, {%1, %2};" : "=l"(d) : "f"(lo), "f"(hi));
    return d;
}
__device__ __forceinline__ void unpack2(u64 v, float& lo, float& hi) {
    asm("mov.b64 {%0, %1}, %2;" : "=f"(lo), "=f"(hi) : "l"(v));
}

// ---------- cp.async ----------
__device__ __forceinline__ void cp_async16(unsigned dst, const void* src) {
    asm volatile("cp.async.cg.shared.global [%0], [%1], 16;" :: "r"(dst), "l"(src));
}
__device__ __forceinline__ void cp_commit() {
    asm volatile("cp.async.commit_group;" ::: "memory");
}
__device__ __forceinline__ void cp_wait_all() {
    asm volatile("cp.async.wait_group 0;" ::: "memory");
}

// Plain 64KB weight copy (row-major [k][j], stride 128 floats).
__device__ __forceinline__ void prefetch_w(const float* __restrict__ src,
                                           float* dstf, int tid) {
    unsigned dstb = (unsigned)__cvta_generic_to_shared(dstf);
#pragma unroll
    for (int i = 0; i < 16; ++i) {
        const int off = (tid + i * NTHR) * 16;   // bytes
        cp_async16(dstb + off, (const char*)src + off);
    }
}

// Accumulators: a[jp][mi] = f32x2 (row j0+2jp, row j0+2jp+1) at m-col mq*4+mi.
struct Acc { u64 a[2][4]; };
__device__ __forceinline__ void acc_zero(Acc& A) {
#pragma unroll
    for (int j = 0; j < 2; ++j)
#pragma unroll
        for (int m = 0; m < 4; ++m) A.a[j][m] = 0ull;
}

// Partial GEMM over a 64-row k-half. Both streams strictly affine in k:
// weights advance by HID floats/row, acts by ASTR floats/row. Zero slot ALU.
// Reads are broadcast (1 weight + 1 act address per 8-lane phase pair).
__device__ __forceinline__ void mm_pass(Acc& A, const float* __restrict__ wp,
                                        const float* __restrict__ ap) {
#pragma unroll 4
    for (int kk = 0; kk < 64; ++kk) {
        const float4 w4 = *reinterpret_cast<const float4*>(wp + kk * HID);
        const float4 a4 = *reinterpret_cast<const float4*>(ap + kk * ASTR);
        const u64 wp0 = pack2(w4.x, w4.y);   // natural register pairs (elidable)
        const u64 wp1 = pack2(w4.z, w4.w);
        const u64 a0 = pack2(a4.x, a4.x);    // 4 real dup movs
        const u64 a1 = pack2(a4.y, a4.y);
        const u64 a2 = pack2(a4.z, a4.z);
        const u64 a3 = pack2(a4.w, a4.w);
        A.a[0][0] = ffma2(wp0, a0, A.a[0][0]);
        A.a[0][1] = ffma2(wp0, a1, A.a[0][1]);
        A.a[0][2] = ffma2(wp0, a2, A.a[0][2]);
        A.a[0][3] = ffma2(wp0, a3, A.a[0][3]);
        A.a[1][0] = ffma2(wp1, a0, A.a[1][0]);
        A.a[1][1] = ffma2(wp1, a1, A.a[1][1]);
        A.a[1][2] = ffma2(wp1, a2, A.a[1][2]);
        A.a[1][3] = ffma2(wp1, a3, A.a[1][3]);
    }
}

// k-half reduction (lane ^ 16) + bias + optional residual + leaky + store.
// kh=0 lane stores rows j0,j0+1; kh=1 stores rows j0+2,j0+3; m-quad mq.
// Stores are 2-way bank-conflicted (aligned stride), negligible per layer.
__device__ __forceinline__ void epi(Acc& A, const float* __restrict__ bias,
                                    float* __restrict__ dst,
                                    const float* __restrict__ res, bool hasRes,
                                    int j0, int kh, int mq) {
#pragma unroll
    for (int jp = 0; jp < 2; ++jp)
#pragma unroll
        for (int m = 0; m < 4; ++m) {
            float lo, hi;
            unpack2(A.a[jp][m], lo, hi);
            lo += __shfl_xor_sync(0xffffffffu, lo, 16);
            hi += __shfl_xor_sync(0xffffffffu, hi, 16);
            A.a[jp][m] = pack2(lo, hi);
        }
    u64 v0 = kh ? A.a[1][0] : A.a[0][0];
    u64 v1 = kh ? A.a[1][1] : A.a[0][1];
    u64 v2 = kh ? A.a[1][2] : A.a[0][2];
    u64 v3 = kh ? A.a[1][3] : A.a[0][3];
    const int r1 = j0 + 2 * kh;
    const int r2 = r1 + 1;
    float x0, x1, x2, x3, y0, y1, y2, y3;
    unpack2(v0, x0, y0); unpack2(v1, x1, y1);
    unpack2(v2, x2, y2); unpack2(v3, x3, y3);
    const float b1 = __ldg(bias + r1);
    const float b2 = __ldg(bias + r2);
    x0 += b1; x1 += b1; x2 += b1; x3 += b1;
    y0 += b2; y1 += b2; y2 += b2; y3 += b2;
    const int a1o = r1 * ASTR + mq * 4;
    const int a2o = r2 * ASTR + mq * 4;
    if (hasRes) {
        const float4 rA = *reinterpret_cast<const float4*>(res + a1o);
        const float4 rB = *reinterpret_cast<const float4*>(res + a2o);
        x0 += rA.x; x1 += rA.y; x2 += rA.z; x3 += rA.w;
        y0 += rB.x; y1 += rB.y; y2 += rB.z; y3 += rB.w;
    }
    x0 = fmaxf(x0, NEGS * x0); x1 = fmaxf(x1, NEGS * x1);
    x2 = fmaxf(x2, NEGS * x2); x3 = fmaxf(x3, NEGS * x3);
    y0 = fmaxf(y0, NEGS * y0); y1 = fmaxf(y1, NEGS * y1);
    y2 = fmaxf(y2, NEGS * y2); y3 = fmaxf(y3, NEGS * y3);
    *reinterpret_cast<float4*>(dst + a1o) = make_float4(x0, x1, x2, x3);
    *reinterpret_cast<float4*>(dst + a2o) = make_float4(y0, y1, y2, y3);
}

template <bool RES>
__device__ __forceinline__ void full_layer(const float* __restrict__ Wsm,
                                           const float* __restrict__ b,
                                           const float* __restrict__ hin,
                                           float* __restrict__ hout,
                                           int k0, int j0, int kh, int mq) {
    Acc A; acc_zero(A);
    mm_pass(A, Wsm + k0 * HID + j0, hin + k0 * ASTR + mq * 4);
    epi(A, b, hout, hout, RES, j0, kh, mq);
}

// Small-K input layer: thread computes its 2 rows x 4 m fully.
__device__ __forceinline__ void input_layer(const float* __restrict__ Win,
                                            const float* __restrict__ bin,
                                            const float* __restrict__ xsT,
                                            int coff, int K,
                                            float* __restrict__ dst,
                                            int j0, int kh, int mq) {
    const int r1 = j0 + 2 * kh;
    const int r2 = r1 + 1;
    const int m0 = mq * 4;
    float y1[4] = {}, y2[4] = {};
    for (int k = 0; k < K; ++k) {
        const float w1 = __ldg(Win + k * HID + r1);
        const float w2 = __ldg(Win + k * HID + r2);
        const float4 a = *reinterpret_cast<const float4*>(xsT + (coff + k) * 16 + m0);
        y1[0] = fmaf(w1, a.x, y1[0]); y1[1] = fmaf(w1, a.y, y1[1]);
        y1[2] = fmaf(w1, a.z, y1[2]); y1[3] = fmaf(w1, a.w, y1[3]);
        y2[0] = fmaf(w2, a.x, y2[0]); y2[1] = fmaf(w2, a.y, y2[1]);
        y2[2] = fmaf(w2, a.z, y2[2]); y2[3] = fmaf(w2, a.w, y2[3]);
    }
    const float b1 = __ldg(bin + r1);
    const float b2 = __ldg(bin + r2);
#pragma unroll
    for (int i = 0; i < 4; ++i) {
        y1[i] += b1; y1[i] = fmaxf(y1[i], NEGS * y1[i]);
        y2[i] += b2; y2[i] = fmaxf(y2[i], NEGS * y2[i]);
    }
    *reinterpret_cast<float4*>(dst + r1 * ASTR + m0) = make_float4(y1[0], y1[1], y1[2], y1[3]);
    *reinterpret_cast<float4*>(dst + r2 * ASTR + m0) = make_float4(y2[0], y2[1], y2[2], y2[3]);
}

__global__ void __launch_bounds__(NTHR, 1)
hedger_kernel(const float* __restrict__ feats,
              const float* __restrict__ fw_in, const float* __restrict__ fb_in,
              const float* __restrict__ fr1_w1, const float* __restrict__ fr1_b1,
              const float* __restrict__ fr1_w2, const float* __restrict__ fr1_b2,
              const float* __restrict__ fr2_w1, const float* __restrict__ fr2_b1,
              const float* __restrict__ fr2_w2, const float* __restrict__ fr2_b2,
              const float* __restrict__ pw_in, const float* __restrict__ pb_in,
              const float* __restrict__ pr1_w1, const float* __restrict__ pr1_b1,
              const float* __restrict__ pr1_w2, const float* __restrict__ pr1_b2,
              const float* __restrict__ pr2_w1, const float* __restrict__ pr2_b1,
              const float* __restrict__ pr2_w2, const float* __restrict__ pr2_b2,
              const float* __restrict__ cw1, const float* __restrict__ cb1,
              const float* __restrict__ cw2, const float* __restrict__ cb2,
              float* __restrict__ out) {
    extern __shared__ float sm[];
    float* wb0  = sm + WB0;
    float* wb1  = sm + WB1;
    float* hb_f = sm + HB_F;
    float* ht_f = sm + HT_F;
    float* hb_p = sm + HB_P;
    float* ht_p = sm + HT_P;
    float* xsT  = sm + XST;
    float* ds   = sm + DSO;

    const int tid  = threadIdx.x;
    const int lane = tid & 31;
    const int warp = tid >> 5;
    const int kh   = lane >> 4;                  // 0/1 k-half
    const int t    = lane & 15;
    const int j0   = ((warp & 1) * 16 + t) * 4;  // j-quad base, 0..124
    const int mq   = warp >> 1;                  // 0..3 m-quad
    const int k0   = kh * 64;
    const int b0   = blockIdx.x * MROWS;

    const float cb2v = __ldg(cb2);
    const float* cw1_hi = cw1 + HID * HID;

    prefetch_w(fr1_w1, wb0, tid);
    cp_commit();

    for (int n = 0; n < NSTEP; ++n) {
        // ---- features -> xsT[c][m]; recurrent delta into col 3 ----
        if (tid < MROWS * 12) {
            const int r = tid / 12, c = tid % 12;
            float v = feats[((size_t)(b0 + r) * NSTEP + n) * 12 + c];
            if (c == 3 && n > 0) v = ds[r];
            xsT[c * 16 + r] = v;
        }
        __syncthreads();

        // ---- input layers (tiny K, weights L1-resident) ----
        input_layer(fw_in, fb_in, xsT, 0, 4, hb_f, j0, kh, mq);
        input_layer(pw_in, pb_in, xsT, 4, 8, hb_p, j0, kh, mq);

        // ---- 10 staged 64KB layers, double-buffered ----
        cp_wait_all(); __syncthreads();
        prefetch_w(fr1_w2, wb1, tid); cp_commit();
        full_layer<false>(wb0, fr1_b1, hb_f, ht_f, k0, j0, kh, mq);

        cp_wait_all(); __syncthreads();
        prefetch_w(fr2_w1, wb0, tid); cp_commit();
        full_layer<true >(wb1, fr1_b2, ht_f, hb_f, k0, j0, kh, mq);

        cp_wait_all(); __syncthreads();
        prefetch_w(fr2_w2, wb1, tid); cp_commit();
        full_layer<false>(wb0, fr2_b1, hb_f, ht_f, k0, j0, kh, mq);

        cp_wait_all(); __syncthreads();
        prefetch_w(pr1_w1, wb0, tid); cp_commit();
        full_layer<true >(wb1, fr2_b2, ht_f, hb_f, k0, j0, kh, mq);

        cp_wait_all(); __syncthreads();
        prefetch_w(pr1_w2, wb1, tid); cp_commit();
        full_layer<false>(wb0, pr1_b1, hb_p, ht_p, k0, j0, kh, mq);

        cp_wait_all(); __syncthreads();
        prefetch_w(pr2_w1, wb0, tid); cp_commit();
        full_layer<true >(wb1, pr1_b2, ht_p, hb_p, k0, j0, kh, mq);

        cp_wait_all(); __syncthreads();
        prefetch_w(pr2_w2, wb1, tid); cp_commit();
        full_layer<false>(wb0, pr2_b1, hb_p, ht_p, k0, j0, kh, mq);

        cp_wait_all(); __syncthreads();
        prefetch_w(cw1, wb0, tid); cp_commit();
        full_layer<true >(wb1, pr2_b2, ht_p, hb_p, k0, j0, kh, mq);

        // combiner: accumulate both halves of concat(fe, pe) @ cw1
        {
            Acc A; acc_zero(A);
            cp_wait_all(); __syncthreads();
            prefetch_w(cw1_hi, wb1, tid); cp_commit();
            mm_pass(A, wb0 + k0 * HID + j0, hb_f + k0 * ASTR + mq * 4);  // fe @ cw1[0:128]

            cp_wait_all(); __syncthreads();
            prefetch_w(fr1_w1, wb0, tid); cp_commit();                   // wrap: next step's L0
            mm_pass(A, wb1 + k0 * HID + j0, hb_p + k0 * ASTR + mq * 4);  // pe @ cw1[128:256]
            epi(A, cb1, ht_f, nullptr, false, j0, kh, mq);
        }
        __syncthreads();

        // ---- head: sigmoid(hc @ cw2 + cb2) ----
        {
            const int m   = tid >> 4;        // 0..15
            const int seg = tid & 15;        // 16-way j split
            float pacc = 0.0f;
#pragma unroll
            for (int jj = 0; jj < 8; ++jj) {
                const int j = seg * 8 + jj;
                pacc += ht_f[j * ASTR + m] * __ldg(cw2 + j);
            }
            pacc += __shfl_down_sync(0xffffffffu, pacc, 8, 16);
            pacc += __shfl_down_sync(0xffffffffu, pacc, 4, 16);
            pacc += __shfl_down_sync(0xffffffffu, pacc, 2, 16);
            pacc += __shfl_down_sync(0xffffffffu, pacc, 1, 16);
            if (seg == 0) {
                const float d = 1.0f / (1.0f + expf(-(pacc + cb2v)));
                ds[m] = d;
                out[(size_t)(b0 + m) * NSTEP + n] = d;
            }
        }
        __syncthreads();
    }
}

extern "C" void kernel_launch(void* const* d_in, const int* in_sizes, int n_in,
                              void* d_out, int out_size) {
    const float* feats  = (const float*)d_in[0];
    const float* fw_in  = (const float*)d_in[1];
    const float* fb_in  = (const float*)d_in[2];
    const float* fr1_w1 = (const float*)d_in[3];
    const float* fr1_b1 = (const float*)d_in[4];
    const float* fr1_w2 = (const float*)d_in[5];
    const float* fr1_b2 = (const float*)d_in[6];
    const float* fr2_w1 = (const float*)d_in[7];
    const float* fr2_b1 = (const float*)d_in[8];
    const float* fr2_w2 = (const float*)d_in[9];
    const float* fr2_b2 = (const float*)d_in[10];
    const float* pw_in  = (const float*)d_in[11];
    const float* pb_in  = (const float*)d_in[12];
    const float* pr1_w1 = (const float*)d_in[13];
    const float* pr1_b1 = (const float*)d_in[14];
    const float* pr1_w2 = (const float*)d_in[15];
    const float* pr1_b2 = (const float*)d_in[16];
    const float* pr2_w1 = (const float*)d_in[17];
    const float* pr2_b1 = (const float*)d_in[18];
    const float* pr2_w2 = (const float*)d_in[19];
    const float* pr2_b2 = (const float*)d_in[20];
    const float* cw1    = (const float*)d_in[21];
    const float* cb1    = (const float*)d_in[22];
    const float* cw2    = (const float*)d_in[23];
    const float* cb2    = (const float*)d_in[24];

    cudaFuncSetAttribute(hedger_kernel,
                         cudaFuncAttributeMaxDynamicSharedMemorySize, SMEM_BYTES);

    hedger_kernel<<<2048 / MROWS, NTHR, SMEM_BYTES>>>(
        feats,
        fw_in, fb_in,
        fr1_w1, fr1_b1, fr1_w2, fr1_b2,
        fr2_w1, fr2_b1, fr2_w2, fr2_b2,
        pw_in, pb_in,
        pr1_w1, pr1_b1, pr1_w2, pr1_b2,
        pr2_w1, pr2_b1, pr2_w2, pr2_b2,
        cw1, cb1, cw2, cb2,
        (float*)d_out);
}